// round 12
// baseline (speedup 1.0000x reference)
#include <cuda_runtime.h>
#include <cuda_bf16.h>
#include <cstdint>
#include <cstddef>

// 11 weight tiles x {hi,lo} x 16384 bf16, layout [n][k] (n-major), unpadded.
__device__ __nv_bfloat16 g_wpk[11 * 2 * 16384];

// ---------------------------------------------------------------------------
__device__ __forceinline__ uint32_t smem_u32(const void* p) {
    uint32_t a;
    asm("{ .reg .u64 t; cvta.to.shared.u64 t, %1; cvt.u32.u64 %0, t; }" : "=r"(a) : "l"(p));
    return a;
}
__device__ __forceinline__ void ldsm_x4(uint32_t addr, uint32_t* r) {
    asm volatile("ldmatrix.sync.aligned.m8n8.x4.shared.b16 {%0,%1,%2,%3}, [%4];"
        : "=r"(r[0]), "=r"(r[1]), "=r"(r[2]), "=r"(r[3]) : "r"(addr));
}
__device__ __forceinline__ void mma16816(float* d, const uint32_t* a, uint32_t b0, uint32_t b1) {
    asm volatile(
        "mma.sync.aligned.m16n8k16.row.col.f32.bf16.bf16.f32 "
        "{%0,%1,%2,%3}, {%4,%5,%6,%7}, {%8,%9}, {%0,%1,%2,%3};"
        : "+f"(d[0]), "+f"(d[1]), "+f"(d[2]), "+f"(d[3])
        : "r"(a[0]), "r"(a[1]), "r"(a[2]), "r"(a[3]), "r"(b0), "r"(b1));
}
__device__ __forceinline__ uint32_t packbf(float a, float b) {
    __nv_bfloat162 h = __floats2bfloat162_rn(a, b);
    return *reinterpret_cast<uint32_t*>(&h);
}
__device__ __forceinline__ void cp_async16_ca(uint32_t dst, const void* src) {
    asm volatile("cp.async.ca.shared.global [%0], [%1], 16;" :: "r"(dst), "l"(src));
}
#define CP_COMMIT() asm volatile("cp.async.commit_group;" ::: "memory")
#define CP_WAIT(N)  asm volatile("cp.async.wait_group %0;" :: "n"(N) : "memory")

// ---------------------------------------------------------------------------
__global__ void pack_weights(const float* __restrict__ w_in0, const float* __restrict__ w_in1,
                             const float* __restrict__ Wr1, const float* __restrict__ Wr2,
                             const float* __restrict__ w_ang)
{
    if (blockIdx.x == 80) {
        __nv_bfloat16* hi_out = g_wpk + (size_t)10 * 2 * 16384;
        __nv_bfloat16* lo_out = hi_out + 16384;
#pragma unroll
        for (int it = 0; it < 8; it++) {
            int i = it * 256 + threadIdx.x;
            int nn = i >> 7, k = i & 127;
            float v = (nn < 14) ? w_ang[k * 14 + nn] : 0.f;
            __nv_bfloat16 h = __float2bfloat16(v);
            hi_out[i] = h;
            lo_out[i] = __float2bfloat16(v - __bfloat162float(h));
        }
        return;
    }
    int tile = blockIdx.x >> 3;
    int part = blockIdx.x & 7;
    const float* W;
    if (tile < 3)       W = w_in0 + (size_t)tile * 16384;
    else if (tile < 6)  W = w_in1 + (size_t)(tile - 3) * 16384;
    else if (tile == 6) W = Wr1;
    else if (tile == 7) W = Wr2;
    else if (tile == 8) W = Wr1 + 16384;
    else                W = Wr2 + 16384;
    __nv_bfloat16* hi_out = g_wpk + (size_t)tile * 2 * 16384;
    __nv_bfloat16* lo_out = hi_out + 16384;
#pragma unroll
    for (int it = 0; it < 8; it++) {
        int i = part * 2048 + it * 256 + threadIdx.x;
        int nn = i >> 7, k = i & 127;
        float v = W[(size_t)k * 128 + nn];
        __nv_bfloat16 h = __float2bfloat16(v);
        hi_out[i] = h;
        lo_out[i] = __float2bfloat16(v - __bfloat162float(h));
    }
}

// ---------------------------------------------------------------------------
#define LDT        136
#define A_TILE_B   (64 * LDT * 2)
#define B_TILE_B   (128 * LDT * 2)
#define A_HI_OFF   0
#define A_LO_OFF   (A_TILE_B)
#define B_HI_OFF   (2 * A_TILE_B)
#define B_LO_OFF   (B_HI_OFF + B_TILE_B)
#define SU0_OFF    (B_HI_OFF + 8192)
#define SU1_OFF    (SU0_OFF + 3904)
#define SMEM_TOTAL (B_LO_OFF + B_TILE_B)    // 104448

__global__ void __launch_bounds__(256, 2) fused_all(
    const float* __restrict__ rep0, const float* __restrict__ rep1,
    const float* __restrict__ b_in0, const float* __restrict__ b_in1,
    const float* __restrict__ br1, const float* __restrict__ br2,
    const float* __restrict__ b_ang,
    const float* __restrict__ affine,
    const int* __restrict__ aatype,
    const float* __restrict__ frames,
    const int* __restrict__ gidx,
    const float* __restrict__ amask,
    const float* __restrict__ lit,
    float* __restrict__ out, int n)
{
    extern __shared__ char smem[];
    char* A_hi = smem + A_HI_OFF;
    char* A_lo = smem + A_LO_OFF;

    const int tid = threadIdx.x;
    const int wid = tid >> 5;
    const int lane = tid & 31;
    const int wm = wid & 1;
    const int wn = wid >> 1;
    const int row0 = blockIdx.x * 64;

    const uint32_t sb = smem_u32(smem);
    const uint32_t aHi = sb + A_HI_OFF;
    const uint32_t aLo = sb + A_LO_OFF;
    const uint32_t bHi = sb + B_HI_OFF;
    const uint32_t bLo = sb + B_LO_OFF;

    const uint32_t aoff0 = ((wm * 32 + (lane & 15)) * LDT + ((lane >> 4) << 3)) * 2;
    const uint32_t aoff1 = aoff0 + 16 * LDT * 2;
    uint32_t boff[2];
#pragma unroll
    for (int p = 0; p < 2; p++)
        boff[p] = ((wn * 32 + p * 16 + (lane & 7) + ((lane >> 4) << 3)) * LDT
                   + (((lane >> 3) & 1) << 3)) * 2;

    const int ep_r0 = wm * 32 + (lane >> 2);
    const int ep_c0 = wn * 32 + (lane & 3) * 2;

    float acc[2][4][4];
    float res[2][4][4];
#pragma unroll
    for (int i = 0; i < 2; i++)
#pragma unroll
        for (int j = 0; j < 4; j++)
#pragma unroll
            for (int q = 0; q < 4; q++) acc[i][j][q] = 0.f;

    float4 pf[8];   // FULL A-chunk prefetch (res[] is dead during input stages)

    auto issue_B = [&](int t) {
        const char* src = (const char*)(g_wpk + (size_t)t * 2 * 16384);
#pragma unroll
        for (int it = 0; it < 16; it++) {
            int i = it * 256 + tid;
            int half = i >> 11;
            int j = i & 2047;
            int r = j >> 4, ch = j & 15;
            cp_async16_ca(sb + B_HI_OFF + half * B_TILE_B + r * (LDT * 2) + ch * 16,
                          src + (size_t)half * 32768 + (size_t)j * 16);
        }
        CP_COMMIT();
    };

    auto prefetch_A = [&](int g) {
        const float* src = (g < 3) ? rep0 : rep1;
        const int kb = (g % 3) * 128;
#pragma unroll
        for (int it = 0; it < 8; it++) {
            int i = it * 256 + tid;
            int r = i >> 5, c4 = (i & 31) * 4;
            pf[it] = *(const float4*)(src + (size_t)(row0 + r) * 384 + kb + c4);
        }
    };

    auto split_store = [&](float4 v, int r, int c4) {
        v.x = fmaxf(v.x, 0.f); v.y = fmaxf(v.y, 0.f);
        v.z = fmaxf(v.z, 0.f); v.w = fmaxf(v.w, 0.f);
        __nv_bfloat16 h0 = __float2bfloat16(v.x), h1 = __float2bfloat16(v.y);
        __nv_bfloat16 h2 = __float2bfloat16(v.z), h3 = __float2bfloat16(v.w);
        uint32_t off = (r * LDT + c4) * 2;
        uint2 ph, pl;
        ph.x = packbf(__bfloat162float(h0), __bfloat162float(h1));
        ph.y = packbf(__bfloat162float(h2), __bfloat162float(h3));
        pl.x = packbf(v.x - __bfloat162float(h0), v.y - __bfloat162float(h1));
        pl.y = packbf(v.z - __bfloat162float(h2), v.w - __bfloat162float(h3));
        *(uint2*)(A_hi + off) = ph;
        *(uint2*)(A_lo + off) = pl;
    };

    auto store_A_pf = [&]() {
#pragma unroll
        for (int it = 0; it < 8; it++) {
            int i = it * 256 + tid;
            split_store(pf[it], i >> 5, (i & 31) * 4);
        }
    };

    auto epilogue = [&](int s) {
#pragma unroll
        for (int i = 0; i < 2; i++)
#pragma unroll
            for (int j = 0; j < 4; j++) {
                int c = ep_c0 + (j >> 1) * 16 + (j & 1) * 8;
                float bb0, bb1;
                if (s == 5)           { bb0 = b_in0[c] + b_in1[c]; bb1 = b_in0[c + 1] + b_in1[c + 1]; }
                else if ((s - 6) & 1) { bb0 = br2[((s - 6) >> 1) * 128 + c]; bb1 = br2[((s - 6) >> 1) * 128 + c + 1]; }
                else                  { bb0 = br1[((s - 6) >> 1) * 128 + c]; bb1 = br1[((s - 6) >> 1) * 128 + c + 1]; }
                const bool addres = (s >= 6) && ((s - 6) & 1);
                const bool keep = (s == 5) || addres;
#pragma unroll
                for (int half = 0; half < 2; half++) {
                    int r = ep_r0 + i * 16 + half * 8;
                    float x0 = acc[i][j][2 * half] + bb0;
                    float x1 = acc[i][j][2 * half + 1] + bb1;
                    if (addres) {
                        x0 += res[i][j][2 * half];
                        x1 += res[i][j][2 * half + 1];
                    }
                    if (keep) {
                        res[i][j][2 * half] = x0;
                        res[i][j][2 * half + 1] = x1;
                    }
                    float p0 = fmaxf(x0, 0.f), p1 = fmaxf(x1, 0.f);
                    __nv_bfloat16 h0 = __float2bfloat16(p0), h1 = __float2bfloat16(p1);
                    *(uint32_t*)(A_hi + (r * LDT + c) * 2) =
                        packbf(__bfloat162float(h0), __bfloat162float(h1));
                    *(uint32_t*)(A_lo + (r * LDT + c) * 2) =
                        packbf(p0 - __bfloat162float(h0), p1 - __bfloat162float(h1));
                }
            }
    };

    // ============ 10 GEMM stages ==========================================
    prefetch_A(0);
    issue_B(0);

    for (int g = 0; g < 10; g++) {
        if (g < 6) {
            store_A_pf();                      // A(g) entirely from registers
            if (g + 1 < 6) prefetch_A(g + 1);  // LDGs hide under gemm(g)
        }
        CP_WAIT(0);
        __syncthreads();

#pragma unroll
        for (int ks = 0; ks < 8; ks++) {
            const uint32_t kb2 = ks * 32;
            uint32_t ah[2][4], al[2][4], bh[2][4], bl[2][4];
            ldsm_x4(aHi + aoff0 + kb2, ah[0]);
            ldsm_x4(aHi + aoff1 + kb2, ah[1]);
            ldsm_x4(aLo + aoff0 + kb2, al[0]);
            ldsm_x4(aLo + aoff1 + kb2, al[1]);
#pragma unroll
            for (int p = 0; p < 2; p++) {
                ldsm_x4(bHi + boff[p] + kb2, bh[p]);
                ldsm_x4(bLo + boff[p] + kb2, bl[p]);
            }
#pragma unroll
            for (int i = 0; i < 2; i++)
#pragma unroll
                for (int p = 0; p < 2; p++)
#pragma unroll
                    for (int hh = 0; hh < 2; hh++) {
                        float* d = acc[i][2 * p + hh];
                        mma16816(d, ah[i], bh[p][2 * hh], bh[p][2 * hh + 1]);
                        mma16816(d, ah[i], bl[p][2 * hh], bl[p][2 * hh + 1]);
                        mma16816(d, al[i], bh[p][2 * hh], bh[p][2 * hh + 1]);
                    }
        }
        __syncthreads();

        if (g == 9) break;
        issue_B(g + 1);
        if (g >= 5) {
            epilogue(g);
#pragma unroll
            for (int i = 0; i < 2; i++)
#pragma unroll
                for (int j = 0; j < 4; j++)
#pragma unroll
                    for (int q = 0; q < 4; q++) acc[i][j][q] = 0.f;
        }
    }

    // ============ angle GEMM (split across both warp-column groups) =======
    {
        const char* src = (const char*)(g_wpk + (size_t)10 * 2 * 16384);
#pragma unroll
        for (int it = 0; it < 2; it++) {
            int idx = it * 256 + tid;
            int half = idx >> 8;
            int j = idx & 255;
            int r = j >> 4, ch = j & 15;
            cp_async16_ca(sb + B_HI_OFF + half * B_TILE_B + r * (LDT * 2) + ch * 16,
                          src + (size_t)half * 32768 + (size_t)j * 16);
        }
        CP_COMMIT();
    }
    epilogue(9);
    CP_WAIT(0);
    __syncthreads();

    float* sU0 = (float*)(smem + SU0_OFF);
    float* sU1 = (float*)(smem + SU1_OFF);

    if (wn < 2) {
        const uint32_t aboff = (((lane & 7) + ((lane >> 4) << 3)) * LDT
                                + (((lane >> 3) & 1) << 3)) * 2;
        float uacc[2][2][4];
#pragma unroll
        for (int i = 0; i < 2; i++)
#pragma unroll
            for (int h = 0; h < 2; h++)
#pragma unroll
                for (int q = 0; q < 4; q++) uacc[i][h][q] = 0.f;
#pragma unroll
        for (int ksl = 0; ksl < 4; ksl++) {
            const uint32_t kb2 = (wn * 4 + ksl) * 32;
            uint32_t ah[2][4], al[2][4], bh[4], bl[4];
            ldsm_x4(aHi + aoff0 + kb2, ah[0]);
            ldsm_x4(aHi + aoff1 + kb2, ah[1]);
            ldsm_x4(aLo + aoff0 + kb2, al[0]);
            ldsm_x4(aLo + aoff1 + kb2, al[1]);
            ldsm_x4(bHi + aboff + kb2, bh);
            ldsm_x4(bLo + aboff + kb2, bl);
#pragma unroll
            for (int i = 0; i < 2; i++)
#pragma unroll
                for (int hh = 0; hh < 2; hh++) {
                    float* d = uacc[i][hh];
                    mma16816(d, ah[i], bh[2 * hh], bh[2 * hh + 1]);
                    mma16816(d, ah[i], bl[2 * hh], bl[2 * hh + 1]);
                    mma16816(d, al[i], bh[2 * hh], bh[2 * hh + 1]);
                }
        }
        float* sU = wn ? sU1 : sU0;
#pragma unroll
        for (int i = 0; i < 2; i++)
#pragma unroll
            for (int hh = 0; hh < 2; hh++) {
                int c = (lane & 3) * 2 + hh * 8;
                if (c < 14) {
                    float bb0 = wn ? 0.f : b_ang[c];
                    float bb1 = wn ? 0.f : b_ang[c + 1];
#pragma unroll
                    for (int half = 0; half < 2; half++) {
                        int r = ep_r0 + i * 16 + half * 8;
                        sU[r * 15 + c]     = uacc[i][hh][2 * half] + bb0;
                        sU[r * 15 + c + 1] = uacc[i][hh][2 * half + 1] + bb1;
                    }
                }
            }
    }
    __syncthreads();

    // ============ per-residue geometry (threads 0-63) =====================
    const size_t nsz = (size_t)n;
    float* out_ang = out;
    float* out_un  = out + nsz * 14;
    float* out_pos = out + nsz * 28;
    float* out_rg  = out + nsz * 70;
    float* out_tg  = out + nsz * 142;
    float* sRT = (float*)(smem + A_HI_OFF);

    if (tid < 64) {
        const int r = row0 + tid;

        float u[14];
#pragma unroll
        for (int j = 0; j < 14; j++) u[j] = sU0[tid * 15 + j] + sU1[tid * 15 + j];

        float sv[8], cv[8];
        sv[0] = 0.f; cv[0] = 1.f;
#pragma unroll
        for (int g = 0; g < 7; g++) {
            float s0 = u[2 * g], c0 = u[2 * g + 1];
            float inv = rsqrtf(fmaxf(s0 * s0 + c0 * c0, 1e-12f));
            float a0 = s0 * inv, a1 = c0 * inv;
            *(float2*)(out_ang + (size_t)r * 14 + 2 * g) = make_float2(a0, a1);
            sv[g + 1] = a0;
            cv[g + 1] = a1;
        }
#pragma unroll
        for (int j = 0; j < 7; j++)
            *(float2*)(out_un + (size_t)r * 14 + 2 * j) = make_float2(u[2 * j], u[2 * j + 1]);

        const float* af = affine + (size_t)r * 7;
        float qw = af[0], qx = af[1], qy = af[2], qz = af[3];
        float qinv = rsqrtf(fmaxf(qw * qw + qx * qx + qy * qy + qz * qz, 1e-12f));
        qw *= qinv; qx *= qinv; qy *= qinv; qz *= qinv;
        float rb[9];
        rb[0] = 1.f - 2.f * (qy * qy + qz * qz);
        rb[1] = 2.f * (qx * qy - qw * qz);
        rb[2] = 2.f * (qx * qz + qw * qy);
        rb[3] = 2.f * (qx * qy + qw * qz);
        rb[4] = 1.f - 2.f * (qx * qx + qz * qz);
        rb[5] = 2.f * (qy * qz - qw * qx);
        rb[6] = 2.f * (qx * qz - qw * qy);
        rb[7] = 2.f * (qy * qz + qw * qx);
        rb[8] = 1.f - 2.f * (qx * qx + qy * qy);
        const float tb0 = af[4], tb1 = af[5], tb2 = af[6];

        const int at = aatype[r];
        const float* mf = frames + (size_t)at * 128;

        float prevR[9], prevT[3];
#pragma unroll
        for (int g = 0; g < 8; g++) {
            float rg[9], tg[3];
#pragma unroll
            for (int i = 0; i < 3; i++) {
                float m0 = mf[g * 16 + i * 4 + 0];
                float m1 = mf[g * 16 + i * 4 + 1];
                float m2 = mf[g * 16 + i * 4 + 2];
                float m3 = mf[g * 16 + i * 4 + 3];
                rg[i * 3 + 0] = m0;
                rg[i * 3 + 1] = m1 * cv[g] + m2 * sv[g];
                rg[i * 3 + 2] = -m1 * sv[g] + m2 * cv[g];
                tg[i] = m3;
            }
            if (g >= 5) {
                float R[9], T[3];
#pragma unroll
                for (int i = 0; i < 3; i++) {
#pragma unroll
                    for (int j = 0; j < 3; j++)
                        R[i * 3 + j] = prevR[i * 3 + 0] * rg[j]
                                     + prevR[i * 3 + 1] * rg[3 + j]
                                     + prevR[i * 3 + 2] * rg[6 + j];
                    T[i] = prevR[i * 3 + 0] * tg[0] + prevR[i * 3 + 1] * tg[1]
                         + prevR[i * 3 + 2] * tg[2] + prevT[i];
                }
#pragma unroll
                for (int i = 0; i < 9; i++) rg[i] = R[i];
#pragma unroll
                for (int i = 0; i < 3; i++) tg[i] = T[i];
            }
            if (g >= 4) {
#pragma unroll
                for (int i = 0; i < 9; i++) prevR[i] = rg[i];
#pragma unroll
                for (int i = 0; i < 3; i++) prevT[i] = tg[i];
            }
            float R[9], T[3];
#pragma unroll
            for (int i = 0; i < 3; i++) {
#pragma unroll
                for (int j = 0; j < 3; j++)
                    R[i * 3 + j] = rb[i * 3 + 0] * rg[j] + rb[i * 3 + 1] * rg[3 + j]
                                 + rb[i * 3 + 2] * rg[6 + j];
            }
            T[0] = rb[0] * tg[0] + rb[1] * tg[1] + rb[2] * tg[2] + tb0;
            T[1] = rb[3] * tg[0] + rb[4] * tg[1] + rb[5] * tg[2] + tb1;
            T[2] = rb[6] * tg[0] + rb[7] * tg[1] + rb[8] * tg[2] + tb2;

            float* rt = sRT + tid * 97 + g * 12;
#pragma unroll
            for (int i = 0; i < 9; i++) rt[i] = R[i];
#pragma unroll
            for (int i = 0; i < 3; i++) rt[9 + i] = T[i];
        }

#pragma unroll
        for (int a = 0; a < 14; a += 2) {
            float pv[6];
#pragma unroll
            for (int s = 0; s < 2; s++) {
                int aa = a + s;
                int ga = gidx[at * 14 + aa];
                float mk = amask[at * 14 + aa];
                float l0 = lit[((size_t)at * 14 + aa) * 3 + 0];
                float l1 = lit[((size_t)at * 14 + aa) * 3 + 1];
                float l2 = lit[((size_t)at * 14 + aa) * 3 + 2];
                const float* rt = sRT + tid * 97 + ga * 12;
                pv[s * 3 + 0] = (rt[0] * l0 + rt[1] * l1 + rt[2] * l2 + rt[9])  * mk;
                pv[s * 3 + 1] = (rt[3] * l0 + rt[4] * l1 + rt[5] * l2 + rt[10]) * mk;
                pv[s * 3 + 2] = (rt[6] * l0 + rt[7] * l1 + rt[8] * l2 + rt[11]) * mk;
            }
            float* dst = out_pos + (size_t)r * 42 + a * 3;
            *(float2*)(dst + 0) = make_float2(pv[0], pv[1]);
            *(float2*)(dst + 2) = make_float2(pv[2], pv[3]);
            *(float2*)(dst + 4) = make_float2(pv[4], pv[5]);
        }
    }
    __syncthreads();

    // ============ cooperative coalesced flush of rot_g / trans_g ==========
    {
        float4* dst_rg = (float4*)(out_rg + (size_t)row0 * 72);
        float4* dst_tg = (float4*)(out_tg + (size_t)row0 * 24);
#pragma unroll
        for (int it = 0; it < 6; it++) {
            int c = it * 256 + tid;
            if (c < 1152) {
                int rl = c / 18, q4 = (c % 18) * 4;
                float4 v;
                float* srt = sRT + rl * 97;
                v.x = srt[((q4 + 0) / 9) * 12 + (q4 + 0) % 9];
                v.y = srt[((q4 + 1) / 9) * 12 + (q4 + 1) % 9];
                v.z = srt[((q4 + 2) / 9) * 12 + (q4 + 2) % 9];
                v.w = srt[((q4 + 3) / 9) * 12 + (q4 + 3) % 9];
                dst_rg[c] = v;
            } else {
                int c2 = c - 1152;
                int rl = c2 / 6, q4 = (c2 % 6) * 4;
                float4 v;
                float* srt = sRT + rl * 97;
                v.x = srt[((q4 + 0) / 3) * 12 + 9 + (q4 + 0) % 3];
                v.y = srt[((q4 + 1) / 3) * 12 + 9 + (q4 + 1) % 3];
                v.z = srt[((q4 + 2) / 3) * 12 + 9 + (q4 + 2) % 3];
                v.w = srt[((q4 + 3) / 3) * 12 + 9 + (q4 + 3) % 3];
                dst_tg[c2] = v;
            }
        }
    }
}

// ---------------------------------------------------------------------------
extern "C" void kernel_launch(void* const* d_in, const int* in_sizes, int n_in,
                              void* d_out, int out_size)
{
    const float* affine = (const float*)d_in[0];
    const float* rep0   = (const float*)d_in[1];
    const float* rep1   = (const float*)d_in[2];
    const int*   aatype = (const int*)d_in[3];
    const float* w_in0  = (const float*)d_in[4];
    const float* b_in0  = (const float*)d_in[5];
    const float* w_in1  = (const float*)d_in[6];
    const float* b_in1  = (const float*)d_in[7];
    const float* Wr1    = (const float*)d_in[8];
    const float* br1    = (const float*)d_in[9];
    const float* Wr2    = (const float*)d_in[10];
    const float* br2    = (const float*)d_in[11];
    const float* w_ang  = (const float*)d_in[12];
    const float* b_ang  = (const float*)d_in[13];
    const float* frames = (const float*)d_in[14];
    const int*   gidx   = (const int*)d_in[15];
    const float* amask  = (const float*)d_in[16];
    const float* lit    = (const float*)d_in[17];
    float* out = (float*)d_out;

    const int n = in_sizes[0] / 7;

    static bool attr_set = false;
    if (!attr_set) {
        cudaFuncSetAttribute(fused_all, cudaFuncAttributeMaxDynamicSharedMemorySize, SMEM_TOTAL);
        attr_set = true;
    }

    pack_weights<<<81, 256>>>(w_in0, w_in1, Wr1, Wr2, w_ang);
    fused_all<<<n / 64, 256, SMEM_TOTAL>>>(rep0, rep1, b_in0, b_in1, br1, br2, b_ang,
                                           affine, aatype, frames, gidx, amask, lit,
                                           out, n);
}

// round 17
// speedup vs baseline: 1.0114x; 1.0114x over previous
#include <cuda_runtime.h>
#include <cuda_bf16.h>
#include <cstdint>
#include <cstddef>

// 11 weight tiles x {hi,lo} x 16384 bf16, layout [n][k] (n-major), unpadded.
__device__ __nv_bfloat16 g_wpk[11 * 2 * 16384];

// ---------------------------------------------------------------------------
__device__ __forceinline__ uint32_t smem_u32(const void* p) {
    uint32_t a;
    asm("{ .reg .u64 t; cvta.to.shared.u64 t, %1; cvt.u32.u64 %0, t; }" : "=r"(a) : "l"(p));
    return a;
}
__device__ __forceinline__ void ldsm_x4(uint32_t addr, uint32_t* r) {
    asm volatile("ldmatrix.sync.aligned.m8n8.x4.shared.b16 {%0,%1,%2,%3}, [%4];"
        : "=r"(r[0]), "=r"(r[1]), "=r"(r[2]), "=r"(r[3]) : "r"(addr));
}
__device__ __forceinline__ void mma16816(float* d, const uint32_t* a, uint32_t b0, uint32_t b1) {
    asm volatile(
        "mma.sync.aligned.m16n8k16.row.col.f32.bf16.bf16.f32 "
        "{%0,%1,%2,%3}, {%4,%5,%6,%7}, {%8,%9}, {%0,%1,%2,%3};"
        : "+f"(d[0]), "+f"(d[1]), "+f"(d[2]), "+f"(d[3])
        : "r"(a[0]), "r"(a[1]), "r"(a[2]), "r"(a[3]), "r"(b0), "r"(b1));
}
__device__ __forceinline__ uint32_t packbf(float a, float b) {
    __nv_bfloat162 h = __floats2bfloat162_rn(a, b);
    return *reinterpret_cast<uint32_t*>(&h);
}
__device__ __forceinline__ void cp_async16_ca(uint32_t dst, const void* src) {
    asm volatile("cp.async.ca.shared.global [%0], [%1], 16;" :: "r"(dst), "l"(src));
}
#define CP_COMMIT() asm volatile("cp.async.commit_group;" ::: "memory")
#define CP_WAIT(N)  asm volatile("cp.async.wait_group %0;" :: "n"(N) : "memory")

// ---------------------------------------------------------------------------
__global__ void pack_weights(const float* __restrict__ w_in0, const float* __restrict__ w_in1,
                             const float* __restrict__ Wr1, const float* __restrict__ Wr2,
                             const float* __restrict__ w_ang)
{
    if (blockIdx.x == 80) {
        __nv_bfloat16* hi_out = g_wpk + (size_t)10 * 2 * 16384;
        __nv_bfloat16* lo_out = hi_out + 16384;
#pragma unroll
        for (int it = 0; it < 8; it++) {
            int i = it * 256 + threadIdx.x;
            int nn = i >> 7, k = i & 127;
            float v = (nn < 14) ? w_ang[k * 14 + nn] : 0.f;
            __nv_bfloat16 h = __float2bfloat16(v);
            hi_out[i] = h;
            lo_out[i] = __float2bfloat16(v - __bfloat162float(h));
        }
        return;
    }
    int tile = blockIdx.x >> 3;
    int part = blockIdx.x & 7;
    const float* W;
    if (tile < 3)       W = w_in0 + (size_t)tile * 16384;
    else if (tile < 6)  W = w_in1 + (size_t)(tile - 3) * 16384;
    else if (tile == 6) W = Wr1;
    else if (tile == 7) W = Wr2;
    else if (tile == 8) W = Wr1 + 16384;
    else                W = Wr2 + 16384;
    __nv_bfloat16* hi_out = g_wpk + (size_t)tile * 2 * 16384;
    __nv_bfloat16* lo_out = hi_out + 16384;
#pragma unroll
    for (int it = 0; it < 8; it++) {
        int i = part * 2048 + it * 256 + threadIdx.x;
        int nn = i >> 7, k = i & 127;
        float v = W[(size_t)k * 128 + nn];
        __nv_bfloat16 h = __float2bfloat16(v);
        hi_out[i] = h;
        lo_out[i] = __float2bfloat16(v - __bfloat162float(h));
    }
}

// ---------------------------------------------------------------------------
#define LDT        136
#define A_TILE_B   (64 * LDT * 2)
#define B_TILE_B   (128 * LDT * 2)
#define A_HI_OFF   0
#define A_LO_OFF   (A_TILE_B)
#define B_HI_OFF   (2 * A_TILE_B)
#define B_LO_OFF   (B_HI_OFF + B_TILE_B)
#define SU0_OFF    (B_HI_OFF + 8192)
#define SU1_OFF    (SU0_OFF + 3904)
#define SMEM_TOTAL (B_LO_OFF + B_TILE_B)    // 104448

__global__ void __launch_bounds__(256, 2) fused_all(
    const float* __restrict__ rep0, const float* __restrict__ rep1,
    const float* __restrict__ b_in0, const float* __restrict__ b_in1,
    const float* __restrict__ br1, const float* __restrict__ br2,
    const float* __restrict__ b_ang,
    const float* __restrict__ affine,
    const int* __restrict__ aatype,
    const float* __restrict__ frames,
    const int* __restrict__ gidx,
    const float* __restrict__ amask,
    const float* __restrict__ lit,
    float* __restrict__ out, int n)
{
    extern __shared__ char smem[];
    char* A_hi = smem + A_HI_OFF;
    char* A_lo = smem + A_LO_OFF;

    const int tid = threadIdx.x;
    const int wid = tid >> 5;
    const int lane = tid & 31;
    const int wm = wid & 1;
    const int wn = wid >> 1;
    const int row0 = blockIdx.x * 64;

    const uint32_t sb = smem_u32(smem);
    const uint32_t aHi = sb + A_HI_OFF;
    const uint32_t aLo = sb + A_LO_OFF;
    const uint32_t bHi = sb + B_HI_OFF;
    const uint32_t bLo = sb + B_LO_OFF;

    const uint32_t aoff0 = ((wm * 32 + (lane & 15)) * LDT + ((lane >> 4) << 3)) * 2;
    const uint32_t aoff1 = aoff0 + 16 * LDT * 2;
    uint32_t boff[2];
#pragma unroll
    for (int p = 0; p < 2; p++)
        boff[p] = ((wn * 32 + p * 16 + (lane & 7) + ((lane >> 4) << 3)) * LDT
                   + (((lane >> 3) & 1) << 3)) * 2;

    const int ep_r0 = wm * 32 + (lane >> 2);
    const int ep_c0 = wn * 32 + (lane & 3) * 2;

    float acc[2][4][4];
    float res[2][4][4];
#pragma unroll
    for (int i = 0; i < 2; i++)
#pragma unroll
        for (int j = 0; j < 4; j++)
#pragma unroll
            for (int q = 0; q < 4; q++) acc[i][j][q] = 0.f;

    float4 pf[4];   // half-chunk A prefetch (rows 0-31 of the k-chunk)

    auto issue_B = [&](int t) {
        const char* src = (const char*)(g_wpk + (size_t)t * 2 * 16384);
#pragma unroll
        for (int it = 0; it < 16; it++) {
            int i = it * 256 + tid;
            int half = i >> 11;
            int j = i & 2047;
            int r = j >> 4, ch = j & 15;
            cp_async16_ca(sb + B_HI_OFF + half * B_TILE_B + r * (LDT * 2) + ch * 16,
                          src + (size_t)half * 32768 + (size_t)j * 16);
        }
        CP_COMMIT();
    };

    auto prefetch_A = [&](int g) {
        const float* src = (g < 3) ? rep0 : rep1;
        const int kb = (g % 3) * 128;
#pragma unroll
        for (int it = 0; it < 4; it++) {
            int i = it * 256 + tid;
            int r = i >> 5, c4 = (i & 31) * 4;
            pf[it] = *(const float4*)(src + (size_t)(row0 + r) * 384 + kb + c4);
        }
    };

    auto split_store = [&](float4 v, int r, int c4) {
        v.x = fmaxf(v.x, 0.f); v.y = fmaxf(v.y, 0.f);
        v.z = fmaxf(v.z, 0.f); v.w = fmaxf(v.w, 0.f);
        __nv_bfloat16 h0 = __float2bfloat16(v.x), h1 = __float2bfloat16(v.y);
        __nv_bfloat16 h2 = __float2bfloat16(v.z), h3 = __float2bfloat16(v.w);
        uint32_t off = (r * LDT + c4) * 2;
        uint2 ph, pl;
        ph.x = packbf(__bfloat162float(h0), __bfloat162float(h1));
        ph.y = packbf(__bfloat162float(h2), __bfloat162float(h3));
        pl.x = packbf(v.x - __bfloat162float(h0), v.y - __bfloat162float(h1));
        pl.y = packbf(v.z - __bfloat162float(h2), v.w - __bfloat162float(h3));
        *(uint2*)(A_hi + off) = ph;
        *(uint2*)(A_lo + off) = pl;
    };

    auto store_A_pf = [&]() {
#pragma unroll
        for (int it = 0; it < 4; it++) {
            int i = it * 256 + tid;
            split_store(pf[it], i >> 5, (i & 31) * 4);
        }
    };

    auto stage_A_rest = [&](int g) {
        const float* src = (g < 3) ? rep0 : rep1;
        const int kb = (g % 3) * 128;
#pragma unroll
        for (int it = 4; it < 8; it++) {
            int i = it * 256 + tid;
            int r = i >> 5, c4 = (i & 31) * 4;
            float4 v = *(const float4*)(src + (size_t)(row0 + r) * 384 + kb + c4);
            split_store(v, r, c4);
        }
    };

    auto epilogue = [&](int s) {
#pragma unroll
        for (int i = 0; i < 2; i++)
#pragma unroll
            for (int j = 0; j < 4; j++) {
                int c = ep_c0 + (j >> 1) * 16 + (j & 1) * 8;
                float bb0, bb1;
                if (s == 5)           { bb0 = b_in0[c] + b_in1[c]; bb1 = b_in0[c + 1] + b_in1[c + 1]; }
                else if ((s - 6) & 1) { bb0 = br2[((s - 6) >> 1) * 128 + c]; bb1 = br2[((s - 6) >> 1) * 128 + c + 1]; }
                else                  { bb0 = br1[((s - 6) >> 1) * 128 + c]; bb1 = br1[((s - 6) >> 1) * 128 + c + 1]; }
                const bool addres = (s >= 6) && ((s - 6) & 1);
                const bool keep = (s == 5) || addres;
#pragma unroll
                for (int half = 0; half < 2; half++) {
                    int r = ep_r0 + i * 16 + half * 8;
                    float x0 = acc[i][j][2 * half] + bb0;
                    float x1 = acc[i][j][2 * half + 1] + bb1;
                    if (addres) {
                        x0 += res[i][j][2 * half];
                        x1 += res[i][j][2 * half + 1];
                    }
                    if (keep) {
                        res[i][j][2 * half] = x0;
                        res[i][j][2 * half + 1] = x1;
                    }
                    float p0 = fmaxf(x0, 0.f), p1 = fmaxf(x1, 0.f);
                    __nv_bfloat16 h0 = __float2bfloat16(p0), h1 = __float2bfloat16(p1);
                    *(uint32_t*)(A_hi + (r * LDT + c) * 2) =
                        packbf(__bfloat162float(h0), __bfloat162float(h1));
                    *(uint32_t*)(A_lo + (r * LDT + c) * 2) =
                        packbf(p0 - __bfloat162float(h0), p1 - __bfloat162float(h1));
                }
            }
    };

    // ============ 10 GEMM stages ==========================================
    prefetch_A(0);
    issue_B(0);

    for (int g = 0; g < 10; g++) {
        if (g < 6) {
            store_A_pf();
            stage_A_rest(g);
            if (g + 1 < 6) prefetch_A(g + 1);
        }
        CP_WAIT(0);
        __syncthreads();

#pragma unroll
        for (int ks = 0; ks < 8; ks++) {
            const uint32_t kb2 = ks * 32;
            uint32_t ah[2][4], al[2][4], bh[2][4], bl[2][4];
            ldsm_x4(aHi + aoff0 + kb2, ah[0]);
            ldsm_x4(aHi + aoff1 + kb2, ah[1]);
            ldsm_x4(aLo + aoff0 + kb2, al[0]);
            ldsm_x4(aLo + aoff1 + kb2, al[1]);
#pragma unroll
            for (int p = 0; p < 2; p++) {
                ldsm_x4(bHi + boff[p] + kb2, bh[p]);
                ldsm_x4(bLo + boff[p] + kb2, bl[p]);
            }
#pragma unroll
            for (int i = 0; i < 2; i++)
#pragma unroll
                for (int p = 0; p < 2; p++)
#pragma unroll
                    for (int hh = 0; hh < 2; hh++) {
                        float* d = acc[i][2 * p + hh];
                        mma16816(d, ah[i], bh[p][2 * hh], bh[p][2 * hh + 1]);
                        mma16816(d, ah[i], bl[p][2 * hh], bl[p][2 * hh + 1]);
                        mma16816(d, al[i], bh[p][2 * hh], bh[p][2 * hh + 1]);
                    }
        }
        __syncthreads();

        if (g == 9) break;
        issue_B(g + 1);
        if (g >= 5) {
            epilogue(g);
#pragma unroll
            for (int i = 0; i < 2; i++)
#pragma unroll
                for (int j = 0; j < 4; j++)
#pragma unroll
                    for (int q = 0; q < 4; q++) acc[i][j][q] = 0.f;
        }
    }

    // ============ angle GEMM (split across both warp-column groups) =======
    {
        const char* src = (const char*)(g_wpk + (size_t)10 * 2 * 16384);
#pragma unroll
        for (int it = 0; it < 2; it++) {
            int idx = it * 256 + tid;
            int half = idx >> 8;
            int j = idx & 255;
            int r = j >> 4, ch = j & 15;
            cp_async16_ca(sb + B_HI_OFF + half * B_TILE_B + r * (LDT * 2) + ch * 16,
                          src + (size_t)half * 32768 + (size_t)j * 16);
        }
        CP_COMMIT();
    }
    epilogue(9);
    CP_WAIT(0);
    __syncthreads();

    float* sU0 = (float*)(smem + SU0_OFF);
    float* sU1 = (float*)(smem + SU1_OFF);

    if (wn < 2) {
        const uint32_t aboff = (((lane & 7) + ((lane >> 4) << 3)) * LDT
                                + (((lane >> 3) & 1) << 3)) * 2;
        float uacc[2][2][4];
#pragma unroll
        for (int i = 0; i < 2; i++)
#pragma unroll
            for (int h = 0; h < 2; h++)
#pragma unroll
                for (int q = 0; q < 4; q++) uacc[i][h][q] = 0.f;
#pragma unroll
        for (int ksl = 0; ksl < 4; ksl++) {
            const uint32_t kb2 = (wn * 4 + ksl) * 32;
            uint32_t ah[2][4], al[2][4], bh[4], bl[4];
            ldsm_x4(aHi + aoff0 + kb2, ah[0]);
            ldsm_x4(aHi + aoff1 + kb2, ah[1]);
            ldsm_x4(aLo + aoff0 + kb2, al[0]);
            ldsm_x4(aLo + aoff1 + kb2, al[1]);
            ldsm_x4(bHi + aboff + kb2, bh);
            ldsm_x4(bLo + aboff + kb2, bl);
#pragma unroll
            for (int i = 0; i < 2; i++)
#pragma unroll
                for (int hh = 0; hh < 2; hh++) {
                    float* d = uacc[i][hh];
                    mma16816(d, ah[i], bh[2 * hh], bh[2 * hh + 1]);
                    mma16816(d, ah[i], bl[2 * hh], bl[2 * hh + 1]);
                    mma16816(d, al[i], bh[2 * hh], bh[2 * hh + 1]);
                }
        }
        float* sU = wn ? sU1 : sU0;
#pragma unroll
        for (int i = 0; i < 2; i++)
#pragma unroll
            for (int hh = 0; hh < 2; hh++) {
                int c = (lane & 3) * 2 + hh * 8;
                if (c < 14) {
                    float bb0 = wn ? 0.f : b_ang[c];
                    float bb1 = wn ? 0.f : b_ang[c + 1];
#pragma unroll
                    for (int half = 0; half < 2; half++) {
                        int r = ep_r0 + i * 16 + half * 8;
                        sU[r * 15 + c]     = uacc[i][hh][2 * half] + bb0;
                        sU[r * 15 + c + 1] = uacc[i][hh][2 * half + 1] + bb1;
                    }
                }
            }
    }
    __syncthreads();

    // ============ per-residue geometry (threads 0-63) =====================
    const size_t nsz = (size_t)n;
    float* out_ang = out;
    float* out_un  = out + nsz * 14;
    float* out_pos = out + nsz * 28;
    float* out_rg  = out + nsz * 70;
    float* out_tg  = out + nsz * 142;
    float* sRT = (float*)(smem + A_HI_OFF);

    if (tid < 64) {
        const int r = row0 + tid;

        float u[14];
#pragma unroll
        for (int j = 0; j < 14; j++) u[j] = sU0[tid * 15 + j] + sU1[tid * 15 + j];

        float sv[8], cv[8];
        sv[0] = 0.f; cv[0] = 1.f;
#pragma unroll
        for (int g = 0; g < 7; g++) {
            float s0 = u[2 * g], c0 = u[2 * g + 1];
            float inv = rsqrtf(fmaxf(s0 * s0 + c0 * c0, 1e-12f));
            float a0 = s0 * inv, a1 = c0 * inv;
            *(float2*)(out_ang + (size_t)r * 14 + 2 * g) = make_float2(a0, a1);
            sv[g + 1] = a0;
            cv[g + 1] = a1;
        }
#pragma unroll
        for (int j = 0; j < 7; j++)
            *(float2*)(out_un + (size_t)r * 14 + 2 * j) = make_float2(u[2 * j], u[2 * j + 1]);

        const float* af = affine + (size_t)r * 7;
        float qw = af[0], qx = af[1], qy = af[2], qz = af[3];
        float qinv = rsqrtf(fmaxf(qw * qw + qx * qx + qy * qy + qz * qz, 1e-12f));
        qw *= qinv; qx *= qinv; qy *= qinv; qz *= qinv;
        float rb[9];
        rb[0] = 1.f - 2.f * (qy * qy + qz * qz);
        rb[1] = 2.f * (qx * qy - qw * qz);
        rb[2] = 2.f * (qx * qz + qw * qy);
        rb[3] = 2.f * (qx * qy + qw * qz);
        rb[4] = 1.f - 2.f * (qx * qx + qz * qz);
        rb[5] = 2.f * (qy * qz - qw * qx);
        rb[6] = 2.f * (qx * qz - qw * qy);
        rb[7] = 2.f * (qy * qz + qw * qx);
        rb[8] = 1.f - 2.f * (qx * qx + qy * qy);
        const float tb0 = af[4], tb1 = af[5], tb2 = af[6];

        const int at = aatype[r];
        const float* mf = frames + (size_t)at * 128;

        float prevR[9], prevT[3];
#pragma unroll
        for (int g = 0; g < 8; g++) {
            float rg[9], tg[3];
#pragma unroll
            for (int i = 0; i < 3; i++) {
                float m0 = mf[g * 16 + i * 4 + 0];
                float m1 = mf[g * 16 + i * 4 + 1];
                float m2 = mf[g * 16 + i * 4 + 2];
                float m3 = mf[g * 16 + i * 4 + 3];
                rg[i * 3 + 0] = m0;
                rg[i * 3 + 1] = m1 * cv[g] + m2 * sv[g];
                rg[i * 3 + 2] = -m1 * sv[g] + m2 * cv[g];
                tg[i] = m3;
            }
            if (g >= 5) {
                float R[9], T[3];
#pragma unroll
                for (int i = 0; i < 3; i++) {
#pragma unroll
                    for (int j = 0; j < 3; j++)
                        R[i * 3 + j] = prevR[i * 3 + 0] * rg[j]
                                     + prevR[i * 3 + 1] * rg[3 + j]
                                     + prevR[i * 3 + 2] * rg[6 + j];
                    T[i] = prevR[i * 3 + 0] * tg[0] + prevR[i * 3 + 1] * tg[1]
                         + prevR[i * 3 + 2] * tg[2] + prevT[i];
                }
#pragma unroll
                for (int i = 0; i < 9; i++) rg[i] = R[i];
#pragma unroll
                for (int i = 0; i < 3; i++) tg[i] = T[i];
            }
            if (g >= 4) {
#pragma unroll
                for (int i = 0; i < 9; i++) prevR[i] = rg[i];
#pragma unroll
                for (int i = 0; i < 3; i++) prevT[i] = tg[i];
            }
            float R[9], T[3];
#pragma unroll
            for (int i = 0; i < 3; i++) {
#pragma unroll
                for (int j = 0; j < 3; j++)
                    R[i * 3 + j] = rb[i * 3 + 0] * rg[j] + rb[i * 3 + 1] * rg[3 + j]
                                 + rb[i * 3 + 2] * rg[6 + j];
            }
            T[0] = rb[0] * tg[0] + rb[1] * tg[1] + rb[2] * tg[2] + tb0;
            T[1] = rb[3] * tg[0] + rb[4] * tg[1] + rb[5] * tg[2] + tb1;
            T[2] = rb[6] * tg[0] + rb[7] * tg[1] + rb[8] * tg[2] + tb2;

            float* rt = sRT + tid * 97 + g * 12;
#pragma unroll
            for (int i = 0; i < 9; i++) rt[i] = R[i];
#pragma unroll
            for (int i = 0; i < 3; i++) rt[9 + i] = T[i];
        }

#pragma unroll
        for (int a = 0; a < 14; a += 2) {
            float pv[6];
#pragma unroll
            for (int s = 0; s < 2; s++) {
                int aa = a + s;
                int ga = gidx[at * 14 + aa];
                float mk = amask[at * 14 + aa];
                float l0 = lit[((size_t)at * 14 + aa) * 3 + 0];
                float l1 = lit[((size_t)at * 14 + aa) * 3 + 1];
                float l2 = lit[((size_t)at * 14 + aa) * 3 + 2];
                const float* rt = sRT + tid * 97 + ga * 12;
                pv[s * 3 + 0] = (rt[0] * l0 + rt[1] * l1 + rt[2] * l2 + rt[9])  * mk;
                pv[s * 3 + 1] = (rt[3] * l0 + rt[4] * l1 + rt[5] * l2 + rt[10]) * mk;
                pv[s * 3 + 2] = (rt[6] * l0 + rt[7] * l1 + rt[8] * l2 + rt[11]) * mk;
            }
            float* dst = out_pos + (size_t)r * 42 + a * 3;
            *(float2*)(dst + 0) = make_float2(pv[0], pv[1]);
            *(float2*)(dst + 2) = make_float2(pv[2], pv[3]);
            *(float2*)(dst + 4) = make_float2(pv[4], pv[5]);
        }
    }
    __syncthreads();

    // ============ cooperative coalesced flush of rot_g / trans_g ==========
    {
        float4* dst_rg = (float4*)(out_rg + (size_t)row0 * 72);
        float4* dst_tg = (float4*)(out_tg + (size_t)row0 * 24);
#pragma unroll
        for (int it = 0; it < 6; it++) {
            int c = it * 256 + tid;
            if (c < 1152) {
                int rl = c / 18, q4 = (c % 18) * 4;
                float4 v;
                float* srt = sRT + rl * 97;
                v.x = srt[((q4 + 0) / 9) * 12 + (q4 + 0) % 9];
                v.y = srt[((q4 + 1) / 9) * 12 + (q4 + 1) % 9];
                v.z = srt[((q4 + 2) / 9) * 12 + (q4 + 2) % 9];
                v.w = srt[((q4 + 3) / 9) * 12 + (q4 + 3) % 9];
                dst_rg[c] = v;
            } else {
                int c2 = c - 1152;
                int rl = c2 / 6, q4 = (c2 % 6) * 4;
                float4 v;
                float* srt = sRT + rl * 97;
                v.x = srt[((q4 + 0) / 3) * 12 + 9 + (q4 + 0) % 3];
                v.y = srt[((q4 + 1) / 3) * 12 + 9 + (q4 + 1) % 3];
                v.z = srt[((q4 + 2) / 3) * 12 + 9 + (q4 + 2) % 3];
                v.w = srt[((q4 + 3) / 3) * 12 + 9 + (q4 + 3) % 3];
                dst_tg[c2] = v;
            }
        }
    }
}

// ---------------------------------------------------------------------------
extern "C" void kernel_launch(void* const* d_in, const int* in_sizes, int n_in,
                              void* d_out, int out_size)
{
    const float* affine = (const float*)d_in[0];
    const float* rep0   = (const float*)d_in[1];
    const float* rep1   = (const float*)d_in[2];
    const int*   aatype = (const int*)d_in[3];
    const float* w_in0  = (const float*)d_in[4];
    const float* b_in0  = (const float*)d_in[5];
    const float* w_in1  = (const float*)d_in[6];
    const float* b_in1  = (const float*)d_in[7];
    const float* Wr1    = (const float*)d_in[8];
    const float* br1    = (const float*)d_in[9];
    const float* Wr2    = (const float*)d_in[10];
    const float* br2    = (const float*)d_in[11];
    const float* w_ang  = (const float*)d_in[12];
    const float* b_ang  = (const float*)d_in[13];
    const float* frames = (const float*)d_in[14];
    const int*   gidx   = (const int*)d_in[15];
    const float* amask  = (const float*)d_in[16];
    const float* lit    = (const float*)d_in[17];
    float* out = (float*)d_out;

    const int n = in_sizes[0] / 7;

    static bool attr_set = false;
    if (!attr_set) {
        cudaFuncSetAttribute(fused_all, cudaFuncAttributeMaxDynamicSharedMemorySize, SMEM_TOTAL);
        attr_set = true;
    }

    pack_weights<<<81, 256>>>(w_in0, w_in1, Wr1, Wr2, w_ang);
    fused_all<<<n / 64, 256, SMEM_TOTAL>>>(rep0, rep1, b_in0, b_in1, br1, br2, b_ang,
                                           affine, aatype, frames, gidx, amask, lit,
                                           out, n);
}